// round 1
// baseline (speedup 1.0000x reference)
#include <cuda_runtime.h>

// MIND loss, 1024x1024. Key reductions:
//  - shifts are multiples of 512 -> 72/80 channels identical (zero-shift field)
//  - 8 near channels are half-plane stitches of 4 basis fields -> masked separable convs
//  - 7x7 Gaussian is separable; Vimg fused into same tiled pass
//  - sum/max via exp2(t - tmax); deterministic 2-stage reduction

#define TX 32
#define TY 16
#define HX (TX + 6)   // 38
#define HY (TY + 6)   // 22
#define PITCH 40
#define NBX 32        // ceil(1010/32)
#define NBY 64        // ceil(1011/16)
#define NBLK (NBX * NBY)

__device__ float g_partials[NBLK];

__constant__ float c_w[7] = {
    0.06475879783294587f, 0.12098536225957168f, 0.17603266338214976f,
    0.19947114020071635f, 0.17603266338214976f, 0.12098536225957168f,
    0.06475879783294587f
};

__device__ __forceinline__ float ex2(float x) {
    float r;
    asm("ex2.approx.ftz.f32 %0, %1;" : "=f"(r) : "f"(x));
    return r;
}

__global__ __launch_bounds__(256, 4)
void mind_main(const float* __restrict__ img1, const float* __restrict__ img2) {
    __shared__ float sf[5][HY][PITCH];   // q0, dx, dy, dd, s1 (pre-blur fields)
    __shared__ float sa[7][TY][PITCH];   // vertical conv: A0,Ax,Ay,AyT,Ad,AdT,As1
    __shared__ float sred[256];

    const int tid = threadIdx.x;
    const int bx0 = 7 + blockIdx.x * TX;
    const int by0 = 7 + blockIdx.y * TY;

    // ---- Load halo tile, build basis fields ----
    for (int i = tid; i < HY * HX; i += 256) {
        int r = i / HX, c = i - r * HX;
        int gy = by0 - 3 + r, gx = bx0 - 3 + c;   // gy,gx >= 4 always
        float q0 = 0.f, fx = 0.f, fy = 0.f, fd = 0.f, s1 = 0.f;
        if (gy < 1024 && gx < 1024) {
            int xo = gx ^ 512, yo = gy ^ 512;
            float a  = img2[gy * 1024 + gx];
            float bx = img2[gy * 1024 + xo];
            float by = img2[yo * 1024 + gx];
            float bd = img2[yo * 1024 + xo];
            q0 = a * a;
            float t;
            t = a - bx; fx = t * t - q0;
            t = a - by; fy = t * t - q0;
            t = a - bd; fd = t * t - q0;
            float a1  = img1[gy * 1024 + gx];
            float b1x = img1[gy * 1024 + xo];
            float b1y = img1[yo * 1024 + gx];
            float u = a1 - b1x, v = a1 - b1y;
            s1 = u * u + v * v + 2.f * a1 * a1;
        }
        sf[0][r][c] = q0; sf[1][r][c] = fx; sf[2][r][c] = fy;
        sf[3][r][c] = fd; sf[4][r][c] = s1;
    }
    __syncthreads();

    // ---- Vertical 7-tap pass (with top/bottom half-plane split for y-masked channels) ----
    for (int i = tid; i < TY * HX; i += 256) {
        int r = i / HX, c = i - r * HX;
        float a0 = 0, ax = 0, ay = 0, ayt = 0, ad = 0, adt = 0, as1 = 0;
#pragma unroll
        for (int k = 0; k < 7; k++) {
            float w = c_w[k];
            int rr = r + k;
            bool top = (by0 - 3 + rr) < 512;
            a0 += w * sf[0][rr][c];
            ax += w * sf[1][rr][c];
            float vy = w * sf[2][rr][c];
            ay += vy; ayt += top ? vy : 0.f;
            float vd = w * sf[3][rr][c];
            ad += vd; adt += top ? vd : 0.f;
            as1 += w * sf[4][rr][c];
        }
        sa[0][r][c] = a0; sa[1][r][c] = ax; sa[2][r][c] = ay; sa[3][r][c] = ayt;
        sa[4][r][c] = ad; sa[5][r][c] = adt; sa[6][r][c] = as1;
    }
    __syncthreads();

    // ---- Horizontal 7-tap pass + per-pixel MIND combine ----
    float psum = 0.f;
    for (int i = tid; i < TY * TX; i += 256) {
        int y = i / TX, x = i - y * TX;
        int oy = by0 + y, ox = bx0 + x;
        float b0 = 0, hax = 0, haxL = 0, hay = 0, hayt = 0;
        float had = 0, hadL = 0, hadt = 0, hadtL = 0, hs1 = 0;
#pragma unroll
        for (int k = 0; k < 7; k++) {
            float w = c_w[k];
            int cc = x + k;
            bool left = (bx0 - 3 + cc) < 512;
            b0 += w * sa[0][y][cc];
            float vx = w * sa[1][y][cc]; hax  += vx; haxL  += left ? vx : 0.f;
            hay  += w * sa[2][y][cc];
            hayt += w * sa[3][y][cc];
            float vd = w * sa[4][y][cc]; had  += vd; hadL  += left ? vd : 0.f;
            float vt = w * sa[5][y][cc]; hadt += vt; hadtL += left ? vt : 0.f;
            hs1 += w * sa[6][y][cc];
        }
        if (oy <= 1017 && ox <= 1016) {
            float vimg = hs1 * 0.25f + 1e-5f;
            float inv = __fdividef(-1.4426950408889634f, vimg);  // -log2(e)/Vimg
            float D[9];
            D[0] = b0;                                   // zero-shifted channel (x72)
            D[1] = b0 + haxL;                            // ( 1, 0)
            D[2] = b0 + hax - haxL;                      // (-1, 0)
            D[3] = b0 + hayt;                            // ( 0, 1)
            D[4] = b0 + hay - hayt;                      // ( 0,-1)
            D[5] = b0 + hadtL;                           // ( 1, 1)
            D[6] = b0 + hadt - hadtL;                    // (-1, 1)
            D[7] = b0 + hadL - hadtL;                    // ( 1,-1)
            D[8] = b0 + (had - hadL) - (hadt - hadtL);   // (-1,-1)
            float t[9];
#pragma unroll
            for (int c2 = 0; c2 < 9; c2++) t[c2] = D[c2] * inv;
            float tm = t[0];
#pragma unroll
            for (int c2 = 1; c2 < 9; c2++) tm = fmaxf(tm, t[c2]);
            float s = 72.f * ex2(t[0] - tm);
#pragma unroll
            for (int c2 = 1; c2 < 9; c2++) s += ex2(t[c2] - tm);
            psum += s;   // = (sum over 80 channels of mind) / max(mind)
        }
    }

    // ---- Deterministic block reduction ----
    sred[tid] = psum;
    __syncthreads();
    for (int s = 128; s > 0; s >>= 1) {
        if (tid < s) sred[tid] += sred[tid + s];
        __syncthreads();
    }
    if (tid == 0) g_partials[blockIdx.y * gridDim.x + blockIdx.x] = sred[0];
}

__global__ __launch_bounds__(1024)
void mind_reduce(float* __restrict__ out) {
    __shared__ float s[1024];
    int tid = threadIdx.x;
    float v = 0.f;
    for (int i = tid; i < NBLK; i += 1024) v += g_partials[i];
    s[tid] = v;
    __syncthreads();
    for (int k = 512; k > 0; k >>= 1) {
        if (tid < k) s[tid] += s[tid + k];
        __syncthreads();
    }
    if (tid == 0) out[0] = s[0] * (float)(1.0 / 81688800.0);  // 80*1011*1010
}

extern "C" void kernel_launch(void* const* d_in, const int* in_sizes, int n_in,
                              void* d_out, int out_size) {
    const float* img1 = (const float*)d_in[0];
    const float* img2 = (const float*)d_in[1];
    dim3 grid(NBX, NBY);
    mind_main<<<grid, 256>>>(img1, img2);
    mind_reduce<<<1, 1024>>>((float*)d_out);
}

// round 2
// speedup vs baseline: 1.0750x; 1.0750x over previous
#include <cuda_runtime.h>

// MIND loss, 1024x1024, single fused kernel.
//  - shifts are multiples of 512 -> 72/80 channels identical (zero-shift field)
//  - masks only switch at x=512/y=512: 95/2048 tiles take a general masked path,
//    the rest take a fast path with only 4 distinct channels {b0x77, b0+ax, b0+ay, b0+ad}
//  - separable 7-tap Gaussian, float2-vectorized passes
//  - deterministic fused reduction (last-block-done)

#define TX 32
#define TY 16
#define HX (TX + 6)   // 38
#define HY (TY + 6)   // 22
#define PITCH 40
#define NBX 32
#define NBY 64
#define NBLK (NBX * NBY)

__device__ float g_partials[NBLK];
__device__ unsigned int g_count;

__constant__ float c_w[7] = {
    0.06475879783294587f, 0.12098536225957168f, 0.17603266338214976f,
    0.19947114020071635f, 0.17603266338214976f, 0.12098536225957168f,
    0.06475879783294587f
};

__device__ __forceinline__ float ex2(float x) {
    float r;
    asm("ex2.approx.ftz.f32 %0, %1;" : "=f"(r) : "f"(x));
    return r;
}

__global__ __launch_bounds__(256, 4)
void mind_main(const float* __restrict__ img1, const float* __restrict__ img2,
               float* __restrict__ out) {
    __shared__ float sf[5][HY][PITCH];   // pre-blur basis fields q0, fx, fy, fd, s1
    __shared__ float sa[7][TY][PITCH];   // vertical conv results (fast path uses 5)
    __shared__ float sred[256];
    __shared__ bool s_last;

    const int tid = threadIdx.x;
    const int bx0 = 7 + blockIdx.x * TX;
    const int by0 = 7 + blockIdx.y * TY;

    // mask boundary straddle tests over the exact tap ranges
    const bool xu = !((bx0 - 3) < 512 && (bx0 + TX + 2) >= 512);
    const bool yu = !((by0 - 3) < 512 && (by0 + TY + 2) >= 512);

    float psum = 0.f;

    if (xu && yu) {
        // ================= FAST PATH (uniform masks) =================
        // ---- load halo, build basis fields, float2 ----
        for (int i = tid; i < HY * (HX / 2); i += 256) {
            int r = i / (HX / 2), c = (i - r * (HX / 2)) * 2;
            int gy = by0 - 3 + r, gx = bx0 - 3 + c;   // gx even, pair in/out together
            float2 q0 = {0.f, 0.f}, fx = q0, fy = q0, fd = q0, s1 = q0;
            if (gy < 1024 && gx < 1024) {
                int yo = gy ^ 512, xo = gx ^ 512;
                float2 a  = *(const float2*)(img2 + gy * 1024 + gx);
                float2 b1 = *(const float2*)(img2 + gy * 1024 + xo);
                float2 b2 = *(const float2*)(img2 + yo * 1024 + gx);
                float2 b3 = *(const float2*)(img2 + yo * 1024 + xo);
                q0.x = a.x * a.x;               q0.y = a.y * a.y;
                float t;
                t = a.x - b1.x; fx.x = t * t - q0.x;  t = a.y - b1.y; fx.y = t * t - q0.y;
                t = a.x - b2.x; fy.x = t * t - q0.x;  t = a.y - b2.y; fy.y = t * t - q0.y;
                t = a.x - b3.x; fd.x = t * t - q0.x;  t = a.y - b3.y; fd.y = t * t - q0.y;
                float2 p  = *(const float2*)(img1 + gy * 1024 + gx);
                float2 px = *(const float2*)(img1 + gy * 1024 + xo);
                float2 py = *(const float2*)(img1 + yo * 1024 + gx);
                float u, v;
                u = p.x - px.x; v = p.x - py.x; s1.x = u * u + v * v + 2.f * p.x * p.x;
                u = p.y - px.y; v = p.y - py.y; s1.y = u * u + v * v + 2.f * p.y * p.y;
            }
            *(float2*)&sf[0][r][c] = q0; *(float2*)&sf[1][r][c] = fx;
            *(float2*)&sf[2][r][c] = fy; *(float2*)&sf[3][r][c] = fd;
            *(float2*)&sf[4][r][c] = s1;
        }
        __syncthreads();

        // ---- vertical 7-tap, 5 planes, float2 ----
        for (int i = tid; i < TY * (HX / 2); i += 256) {
            int r = i / (HX / 2), c = (i - r * (HX / 2)) * 2;
            float2 a0 = {0.f, 0.f}, ax = a0, ay = a0, ad = a0, as1 = a0;
#pragma unroll
            for (int k = 0; k < 7; k++) {
                float w = c_w[k];
                float2 v;
                v = *(const float2*)&sf[0][r + k][c]; a0.x += w * v.x; a0.y += w * v.y;
                v = *(const float2*)&sf[1][r + k][c]; ax.x += w * v.x; ax.y += w * v.y;
                v = *(const float2*)&sf[2][r + k][c]; ay.x += w * v.x; ay.y += w * v.y;
                v = *(const float2*)&sf[3][r + k][c]; ad.x += w * v.x; ad.y += w * v.y;
                v = *(const float2*)&sf[4][r + k][c]; as1.x += w * v.x; as1.y += w * v.y;
            }
            *(float2*)&sa[0][r][c] = a0; *(float2*)&sa[1][r][c] = ax;
            *(float2*)&sa[2][r][c] = ay; *(float2*)&sa[3][r][c] = ad;
            *(float2*)&sa[4][r][c] = as1;
        }
        __syncthreads();

        // ---- horizontal 7-tap over window-of-8, 2 outputs/thread ----
        {
            const int y = tid >> 4;
            const int x0 = (tid & 15) * 2;
            float b0a = 0, b0b = 0, axa = 0, axb = 0, aya = 0, ayb = 0;
            float ada = 0, adb = 0, s1a = 0, s1b = 0;
#pragma unroll
            for (int p = 0; p < 5; p++) {
                float wv[8];
                *(float2*)&wv[0] = *(const float2*)&sa[p][y][x0 + 0];
                *(float2*)&wv[2] = *(const float2*)&sa[p][y][x0 + 2];
                *(float2*)&wv[4] = *(const float2*)&sa[p][y][x0 + 4];
                *(float2*)&wv[6] = *(const float2*)&sa[p][y][x0 + 6];
                float sa_ = 0, sb_ = 0;
#pragma unroll
                for (int k = 0; k < 7; k++) {
                    sa_ += c_w[k] * wv[k];
                    sb_ += c_w[k] * wv[k + 1];
                }
                if (p == 0) { b0a = sa_; b0b = sb_; }
                else if (p == 1) { axa = sa_; axb = sb_; }
                else if (p == 2) { aya = sa_; ayb = sb_; }
                else if (p == 3) { ada = sa_; adb = sb_; }
                else { s1a = sa_; s1b = sb_; }
            }
            const int oy = by0 + y;
            if (oy <= 1017) {
                int ox = bx0 + x0;
                if (ox <= 1016) {
                    float vimg = s1a * 0.25f + 1e-5f;
                    float inv = __fdividef(-1.4426950408889634f, vimg);
                    float t0 = b0a * inv, t1 = (b0a + axa) * inv;
                    float t2 = (b0a + aya) * inv, t3 = (b0a + ada) * inv;
                    float tm = fmaxf(fmaxf(t0, t1), fmaxf(t2, t3));
                    psum += 77.f * ex2(t0 - tm) + ex2(t1 - tm) + ex2(t2 - tm) + ex2(t3 - tm);
                }
                if (ox + 1 <= 1016) {
                    float vimg = s1b * 0.25f + 1e-5f;
                    float inv = __fdividef(-1.4426950408889634f, vimg);
                    float t0 = b0b * inv, t1 = (b0b + axb) * inv;
                    float t2 = (b0b + ayb) * inv, t3 = (b0b + adb) * inv;
                    float tm = fmaxf(fmaxf(t0, t1), fmaxf(t2, t3));
                    psum += 77.f * ex2(t0 - tm) + ex2(t1 - tm) + ex2(t2 - tm) + ex2(t3 - tm);
                }
            }
        }
    } else {
        // ================= GENERAL PATH (boundary-straddling tiles) =================
        for (int i = tid; i < HY * HX; i += 256) {
            int r = i / HX, c = i - r * HX;
            int gy = by0 - 3 + r, gx = bx0 - 3 + c;
            float q0 = 0.f, fx = 0.f, fy = 0.f, fd = 0.f, s1 = 0.f;
            if (gy < 1024 && gx < 1024) {
                int xo = gx ^ 512, yo = gy ^ 512;
                float a  = img2[gy * 1024 + gx];
                float bx = img2[gy * 1024 + xo];
                float by = img2[yo * 1024 + gx];
                float bd = img2[yo * 1024 + xo];
                q0 = a * a;
                float t;
                t = a - bx; fx = t * t - q0;
                t = a - by; fy = t * t - q0;
                t = a - bd; fd = t * t - q0;
                float a1  = img1[gy * 1024 + gx];
                float b1x = img1[gy * 1024 + xo];
                float b1y = img1[yo * 1024 + gx];
                float u = a1 - b1x, v = a1 - b1y;
                s1 = u * u + v * v + 2.f * a1 * a1;
            }
            sf[0][r][c] = q0; sf[1][r][c] = fx; sf[2][r][c] = fy;
            sf[3][r][c] = fd; sf[4][r][c] = s1;
        }
        __syncthreads();

        for (int i = tid; i < TY * HX; i += 256) {
            int r = i / HX, c = i - r * HX;
            float a0 = 0, ax = 0, ay = 0, ayt = 0, ad = 0, adt = 0, as1 = 0;
#pragma unroll
            for (int k = 0; k < 7; k++) {
                float w = c_w[k];
                int rr = r + k;
                bool top = (by0 - 3 + rr) < 512;
                a0 += w * sf[0][rr][c];
                ax += w * sf[1][rr][c];
                float vy = w * sf[2][rr][c];
                ay += vy; ayt += top ? vy : 0.f;
                float vd = w * sf[3][rr][c];
                ad += vd; adt += top ? vd : 0.f;
                as1 += w * sf[4][rr][c];
            }
            sa[0][r][c] = a0; sa[1][r][c] = ax; sa[2][r][c] = ay; sa[3][r][c] = ayt;
            sa[4][r][c] = ad; sa[5][r][c] = adt; sa[6][r][c] = as1;
        }
        __syncthreads();

        for (int i = tid; i < TY * TX; i += 256) {
            int y = i / TX, x = i - y * TX;
            int oy = by0 + y, ox = bx0 + x;
            float b0 = 0, hax = 0, haxL = 0, hay = 0, hayt = 0;
            float had = 0, hadL = 0, hadt = 0, hadtL = 0, hs1 = 0;
#pragma unroll
            for (int k = 0; k < 7; k++) {
                float w = c_w[k];
                int cc = x + k;
                bool left = (bx0 - 3 + cc) < 512;
                b0 += w * sa[0][y][cc];
                float vx = w * sa[1][y][cc]; hax  += vx; haxL  += left ? vx : 0.f;
                hay  += w * sa[2][y][cc];
                hayt += w * sa[3][y][cc];
                float vd = w * sa[4][y][cc]; had  += vd; hadL  += left ? vd : 0.f;
                float vt = w * sa[5][y][cc]; hadt += vt; hadtL += left ? vt : 0.f;
                hs1 += w * sa[6][y][cc];
            }
            if (oy <= 1017 && ox <= 1016) {
                float vimg = hs1 * 0.25f + 1e-5f;
                float inv = __fdividef(-1.4426950408889634f, vimg);
                float D[9];
                D[0] = b0;
                D[1] = b0 + haxL;
                D[2] = b0 + hax - haxL;
                D[3] = b0 + hayt;
                D[4] = b0 + hay - hayt;
                D[5] = b0 + hadtL;
                D[6] = b0 + hadt - hadtL;
                D[7] = b0 + hadL - hadtL;
                D[8] = b0 + (had - hadL) - (hadt - hadtL);
                float t[9];
#pragma unroll
                for (int c2 = 0; c2 < 9; c2++) t[c2] = D[c2] * inv;
                float tm = t[0];
#pragma unroll
                for (int c2 = 1; c2 < 9; c2++) tm = fmaxf(tm, t[c2]);
                float s = 72.f * ex2(t[0] - tm);
#pragma unroll
                for (int c2 = 1; c2 < 9; c2++) s += ex2(t[c2] - tm);
                psum += s;
            }
        }
    }

    // ---- deterministic block reduction ----
    sred[tid] = psum;
    __syncthreads();
    for (int s = 128; s > 0; s >>= 1) {
        if (tid < s) sred[tid] += sred[tid + s];
        __syncthreads();
    }
    if (tid == 0) {
        g_partials[blockIdx.y * NBX + blockIdx.x] = sred[0];
        __threadfence();
        unsigned int v = atomicAdd(&g_count, 1u);
        s_last = (v == NBLK - 1);
    }
    __syncthreads();

    // ---- fused final reduction in the last-arriving block (fixed order: deterministic) ----
    if (s_last) {
        float v = 0.f;
        for (int i = tid; i < NBLK; i += 256) v += g_partials[i];
        __syncthreads();
        sred[tid] = v;
        __syncthreads();
        for (int s = 128; s > 0; s >>= 1) {
            if (tid < s) sred[tid] += sred[tid + s];
            __syncthreads();
        }
        if (tid == 0) {
            out[0] = sred[0] * (float)(1.0 / 81688800.0);  // mean over 80*1011*1010
            g_count = 0;   // reset for next graph replay
        }
    }
}

extern "C" void kernel_launch(void* const* d_in, const int* in_sizes, int n_in,
                              void* d_out, int out_size) {
    const float* img1 = (const float*)d_in[0];
    const float* img2 = (const float*)d_in[1];
    dim3 grid(NBX, NBY);
    mind_main<<<grid, 256>>>(img1, img2, (float*)d_out);
}

// round 3
// speedup vs baseline: 1.1538x; 1.0734x over previous
#include <cuda_runtime.h>

// MIND loss, 1024x1024, single fused kernel, round 3.
//  - shifts multiples of 512 -> 72/80 channels identical; uniform tiles have only
//    4 distinct channels {b0 x77, b0+ax, b0+ay, b0+ad}
//  - fused load+basis+vertical-conv in registers (rolling staggered accumulators,
//    each input read once, NO pre-blur staging in smem)
//  - conv weights as immediates (FFMA-imm, 2x issue rate)
//  - separable 7-tap Gaussian; deterministic fused last-block reduction

#define TX 32
#define TY 24
#define PITCH 40
#define NBX 32
#define NBY 43
#define NBLK (NBX * NBY)

#define CW(k) ((k)==0 ? 0.06475879783294587f : \
               (k)==1 ? 0.12098536225957168f : \
               (k)==2 ? 0.17603266338214976f : \
               (k)==3 ? 0.19947114020071635f : \
               (k)==4 ? 0.17603266338214976f : \
               (k)==5 ? 0.12098536225957168f : \
                        0.06475879783294587f)

__device__ float g_partials[NBLK];
__device__ unsigned int g_count;

__device__ __forceinline__ float ex2(float x) {
    float r;
    asm("ex2.approx.ftz.f32 %0, %1;" : "=f"(r) : "f"(x));
    return r;
}

__global__ __launch_bounds__(256, 5)
void mind_main(const float* __restrict__ img1, const float* __restrict__ img2,
               float* __restrict__ out) {
    __shared__ float sa[7][TY][PITCH];   // vertical-conv planes (fast path uses 5)
    __shared__ float sred[256];
    __shared__ bool s_last;

    const int tid = threadIdx.x;
    const int bx0 = 7 + blockIdx.x * TX;
    const int by0 = 7 + blockIdx.y * TY;

    // uniform-mask tests over the columns/rows actually read (c<=37, rr<=29)
    const bool xu = !((bx0 - 3) < 512 && (bx0 + 34) >= 512);
    const bool yu = !((by0 - 3) < 512 && (by0 + 26) >= 512);

    float psum = 0.f;

    if (xu && yu) {
        // ===================== FAST PATH =====================
        // Phase A: fused load + basis + vertical 7-tap (rolling, 5 planes)
        if (tid < 240) {
            const int c = tid % 40;
            const int g = tid / 40;            // 6 groups of 4 output rows
            const int gx = bx0 - 3 + c;
            const int gy0 = by0 - 3 + g * 4;
            const bool xok = gx < 1024;
            const int xo = gx ^ 512;
            float a0[4] = {0,0,0,0}, a1[4] = {0,0,0,0}, a2[4] = {0,0,0,0};
            float a3[4] = {0,0,0,0}, a4[4] = {0,0,0,0};
#pragma unroll
            for (int i = 0; i < 10; i++) {
                int gy = gy0 + i;
                float v0 = 0.f, v1 = 0.f, v2 = 0.f, v3 = 0.f, v4 = 0.f;
                if (xok && gy < 1024) {
                    int yo = gy ^ 512;
                    float a  = img2[gy * 1024 + gx];
                    float bx = img2[gy * 1024 + xo];
                    float by = img2[yo * 1024 + gx];
                    float bd = img2[yo * 1024 + xo];
                    v0 = a * a;
                    float t;
                    t = a - bx; v1 = t * t - v0;
                    t = a - by; v2 = t * t - v0;
                    t = a - bd; v3 = t * t - v0;
                    float p  = img1[gy * 1024 + gx];
                    float px = img1[gy * 1024 + xo];
                    float py = img1[yo * 1024 + gx];
                    float u = p - px, w = p - py;
                    v4 = u * u + w * w + 2.f * p * p;
                }
#pragma unroll
                for (int j = 0; j < 4; j++) {
                    const int k = i - j;
                    if (k >= 0 && k < 7) {
                        const float w = CW(k);
                        a0[j] += w * v0; a1[j] += w * v1; a2[j] += w * v2;
                        a3[j] += w * v3; a4[j] += w * v4;
                    }
                }
            }
#pragma unroll
            for (int j = 0; j < 4; j++) {
                int r = g * 4 + j;
                sa[0][r][c] = a0[j]; sa[1][r][c] = a1[j]; sa[2][r][c] = a2[j];
                sa[3][r][c] = a3[j]; sa[4][r][c] = a4[j];
            }
        }
        __syncthreads();

        // Phase B: horizontal 7-tap (4 outputs/thread, float4 reads) + combine
        if (tid < 192) {
            const int seg = tid & 7;           // 8 segments x 4 outputs = 32 cols
            const int y = tid >> 3;            // 0..23
            const int x0 = seg * 4;
            float rb0[4], rax[4], ray[4], rad[4], rs1[4];
#pragma unroll
            for (int p = 0; p < 5; p++) {
                float wv[10];
                *(float4*)&wv[0] = *(const float4*)&sa[p][y][x0];
                *(float4*)&wv[4] = *(const float4*)&sa[p][y][x0 + 4];
                *(float2*)&wv[8] = *(const float2*)&sa[p][y][x0 + 8];
                float o0 = 0, o1 = 0, o2 = 0, o3 = 0;
#pragma unroll
                for (int k = 0; k < 7; k++) {
                    const float w = CW(k);
                    o0 += w * wv[k];     o1 += w * wv[k + 1];
                    o2 += w * wv[k + 2]; o3 += w * wv[k + 3];
                }
                if (p == 0)      { rb0[0]=o0; rb0[1]=o1; rb0[2]=o2; rb0[3]=o3; }
                else if (p == 1) { rax[0]=o0; rax[1]=o1; rax[2]=o2; rax[3]=o3; }
                else if (p == 2) { ray[0]=o0; ray[1]=o1; ray[2]=o2; ray[3]=o3; }
                else if (p == 3) { rad[0]=o0; rad[1]=o1; rad[2]=o2; rad[3]=o3; }
                else             { rs1[0]=o0; rs1[1]=o1; rs1[2]=o2; rs1[3]=o3; }
            }
            const int oy = by0 + y;
            if (oy <= 1017) {
#pragma unroll
                for (int j = 0; j < 4; j++) {
                    int ox = bx0 + x0 + j;
                    if (ox <= 1016) {
                        float vimg = rs1[j] * 0.25f + 1e-5f;
                        float inv = __fdividef(-1.4426950408889634f, vimg);
                        float t0 = rb0[j] * inv;
                        float t1 = (rb0[j] + rax[j]) * inv;
                        float t2 = (rb0[j] + ray[j]) * inv;
                        float t3 = (rb0[j] + rad[j]) * inv;
                        float tm = fmaxf(fmaxf(t0, t1), fmaxf(t2, t3));
                        psum += 77.f * ex2(t0 - tm) + ex2(t1 - tm)
                                     + ex2(t2 - tm) + ex2(t3 - tm);
                    }
                }
            }
        }
    } else {
        // ===================== GENERAL PATH (512-boundary tiles) =====================
        // Phase A: rolling vertical conv, 7 planes (with top-masked y variants)
        if (tid < 240) {
            const int c = tid % 40;
            const int g = tid / 40;
            const int gx = bx0 - 3 + c;
            const int gy0 = by0 - 3 + g * 4;
            const bool xok = gx < 1024;
            const int xo = gx ^ 512;
            float a0[4] = {0,0,0,0}, a1[4] = {0,0,0,0}, a2[4] = {0,0,0,0};
            float a2t[4] = {0,0,0,0}, a3[4] = {0,0,0,0}, a3t[4] = {0,0,0,0};
            float a4[4] = {0,0,0,0};
#pragma unroll
            for (int i = 0; i < 10; i++) {
                int gy = gy0 + i;
                float v0 = 0.f, v1 = 0.f, v2 = 0.f, v3 = 0.f, v4 = 0.f;
                if (xok && gy < 1024) {
                    int yo = gy ^ 512;
                    float a  = img2[gy * 1024 + gx];
                    float bx = img2[gy * 1024 + xo];
                    float by = img2[yo * 1024 + gx];
                    float bd = img2[yo * 1024 + xo];
                    v0 = a * a;
                    float t;
                    t = a - bx; v1 = t * t - v0;
                    t = a - by; v2 = t * t - v0;
                    t = a - bd; v3 = t * t - v0;
                    float p  = img1[gy * 1024 + gx];
                    float px = img1[gy * 1024 + xo];
                    float py = img1[yo * 1024 + gx];
                    float u = p - px, w = p - py;
                    v4 = u * u + w * w + 2.f * p * p;
                }
                const bool top = gy < 512;
                float v2t = top ? v2 : 0.f;
                float v3t = top ? v3 : 0.f;
#pragma unroll
                for (int j = 0; j < 4; j++) {
                    const int k = i - j;
                    if (k >= 0 && k < 7) {
                        const float w = CW(k);
                        a0[j] += w * v0;  a1[j] += w * v1;
                        a2[j] += w * v2;  a2t[j] += w * v2t;
                        a3[j] += w * v3;  a3t[j] += w * v3t;
                        a4[j] += w * v4;
                    }
                }
            }
#pragma unroll
            for (int j = 0; j < 4; j++) {
                int r = g * 4 + j;
                sa[0][r][c] = a0[j];  sa[1][r][c] = a1[j];
                sa[2][r][c] = a2[j];  sa[3][r][c] = a2t[j];
                sa[4][r][c] = a3[j];  sa[5][r][c] = a3t[j];
                sa[6][r][c] = a4[j];
            }
        }
        __syncthreads();

        // Phase B: masked horizontal pass + 9-channel combine
        if (tid < 192) {
            const int seg = tid & 7;
            const int y = tid >> 3;
            const int oy = by0 + y;
#pragma unroll
            for (int j = 0; j < 4; j++) {
                const int x = seg * 4 + j;
                const int ox = bx0 + x;
                float b0 = 0, hax = 0, haxL = 0, hay = 0, hayt = 0;
                float had = 0, hadL = 0, hadt = 0, hadtL = 0, hs1 = 0;
#pragma unroll
                for (int k = 0; k < 7; k++) {
                    const float w = CW(k);
                    const int cc = x + k;
                    bool left = (bx0 - 3 + cc) < 512;
                    b0 += w * sa[0][y][cc];
                    float vx = w * sa[1][y][cc]; hax  += vx; haxL  += left ? vx : 0.f;
                    hay  += w * sa[2][y][cc];
                    hayt += w * sa[3][y][cc];
                    float vd = w * sa[4][y][cc]; had  += vd; hadL  += left ? vd : 0.f;
                    float vt = w * sa[5][y][cc]; hadt += vt; hadtL += left ? vt : 0.f;
                    hs1 += w * sa[6][y][cc];
                }
                if (oy <= 1017 && ox <= 1016) {
                    float vimg = hs1 * 0.25f + 1e-5f;
                    float inv = __fdividef(-1.4426950408889634f, vimg);
                    float D[9];
                    D[0] = b0;
                    D[1] = b0 + haxL;
                    D[2] = b0 + hax - haxL;
                    D[3] = b0 + hayt;
                    D[4] = b0 + hay - hayt;
                    D[5] = b0 + hadtL;
                    D[6] = b0 + hadt - hadtL;
                    D[7] = b0 + hadL - hadtL;
                    D[8] = b0 + (had - hadL) - (hadt - hadtL);
                    float t[9];
#pragma unroll
                    for (int c2 = 0; c2 < 9; c2++) t[c2] = D[c2] * inv;
                    float tm = t[0];
#pragma unroll
                    for (int c2 = 1; c2 < 9; c2++) tm = fmaxf(tm, t[c2]);
                    float s = 72.f * ex2(t[0] - tm);
#pragma unroll
                    for (int c2 = 1; c2 < 9; c2++) s += ex2(t[c2] - tm);
                    psum += s;
                }
            }
        }
    }

    // ---- deterministic block reduction ----
    sred[tid] = psum;
    __syncthreads();
    for (int s = 128; s > 0; s >>= 1) {
        if (tid < s) sred[tid] += sred[tid + s];
        __syncthreads();
    }
    if (tid == 0) {
        g_partials[blockIdx.y * NBX + blockIdx.x] = sred[0];
        __threadfence();
        unsigned int v = atomicAdd(&g_count, 1u);
        s_last = (v == NBLK - 1);
    }
    __syncthreads();

    // ---- fused final reduction in last-arriving block (fixed order) ----
    if (s_last) {
        float v = 0.f;
        for (int i = tid; i < NBLK; i += 256) v += g_partials[i];
        __syncthreads();
        sred[tid] = v;
        __syncthreads();
        for (int s = 128; s > 0; s >>= 1) {
            if (tid < s) sred[tid] += sred[tid + s];
            __syncthreads();
        }
        if (tid == 0) {
            out[0] = sred[0] * (float)(1.0 / 81688800.0);  // mean over 80*1011*1010
            g_count = 0;   // reset for next graph replay
        }
    }
}

extern "C" void kernel_launch(void* const* d_in, const int* in_sizes, int n_in,
                              void* d_out, int out_size) {
    const float* img1 = (const float*)d_in[0];
    const float* img2 = (const float*)d_in[1];
    dim3 grid(NBX, NBY);
    mind_main<<<grid, 256>>>(img1, img2, (float*)d_out);
}

// round 4
// speedup vs baseline: 1.1691x; 1.0132x over previous
#include <cuda_runtime.h>

// MIND loss, 1024x1024, round 4.
//  - 72/80 channels identical; uniform tiles need only 4 distinct channels
//  - NEW: cooperative float4 staging of the 7 mirror regions into smem;
//    basis+vertical rolling conv fed by LDS.64 instead of scalar LDG
//  - sa planes alias the raw staging buffer (saves smem, 5 blocks/SM)
//  - shuffle-based deterministic reductions, fused last-block finish

#define TX 32
#define TY 24
#define NBX 32
#define NBY 43
#define NBLK (NBX * NBY)

#define CW(k) ((k)==0 ? 0.06475879783294587f : \
               (k)==1 ? 0.12098536225957168f : \
               (k)==2 ? 0.17603266338214976f : \
               (k)==3 ? 0.19947114020071635f : \
               (k)==4 ? 0.17603266338214976f : \
               (k)==5 ? 0.12098536225957168f : \
                        0.06475879783294587f)

__device__ float g_partials[NBLK];
__device__ unsigned int g_count;

__device__ __forceinline__ float ex2(float x) {
    float r;
    asm("ex2.approx.ftz.f32 %0, %1;" : "=f"(r) : "f"(x));
    return r;
}

__global__ __launch_bounds__(256, 5)
void mind_main(const float* __restrict__ img1, const float* __restrict__ img2,
               float* __restrict__ out) {
    // raw staging: 7 regions x 30 rows x 40 cols = 8400 floats (33.6KB).
    // After Phase A, the first 4800 floats are reused as the 5 sa planes
    // (fast path) or 6720 as 7 planes (general path).
    __shared__ float sraw[8400];
    __shared__ float swr[8];
    __shared__ bool s_last;

    const int tid = threadIdx.x;
    const int bx0 = 7 + blockIdx.x * TX;
    const int by0 = 7 + blockIdx.y * TY;

    const bool xu = !((bx0 - 3) < 512 && (bx0 + 34) >= 512);
    const bool yu = !((by0 - 3) < 512 && (by0 + 26) >= 512);

    float psum = 0.f;

    if (xu && yu) {
        // ===================== FAST PATH =====================
        // ---- Stage: 7 regions, float4 loads, each point loaded once ----
        for (int i = tid; i < 300; i += 256) {
            const int row = i / 10;
            const int q = i - row * 10;
            const int c4 = q * 4;
            const int gy = by0 - 3 + row;
            const int gx = bx0 - 3 + c4;
            const int yo = gy ^ 512;
            const int xo = gx ^ 512;
            float4 vA = {0,0,0,0}, vB = vA, vC = vA, vD = vA;
            float4 vP = vA, vPx = vA, vPy = vA;
            if (gy < 1024) {
                if (gx + 3 < 1024) {
                    vA  = *(const float4*)(img2 + gy * 1024 + gx);
                    vB  = *(const float4*)(img2 + gy * 1024 + xo);
                    vC  = *(const float4*)(img2 + yo * 1024 + gx);
                    vD  = *(const float4*)(img2 + yo * 1024 + xo);
                    vP  = *(const float4*)(img1 + gy * 1024 + gx);
                    vPx = *(const float4*)(img1 + gy * 1024 + xo);
                    vPy = *(const float4*)(img1 + yo * 1024 + gx);
                } else {
                    float t[7][4];
#pragma unroll
                    for (int e = 0; e < 4; e++) {
                        int x = gx + e;
                        bool ok = x < 1024;
                        int xe = x ^ 512;
                        t[0][e] = ok ? img2[gy * 1024 + x]  : 0.f;
                        t[1][e] = ok ? img2[gy * 1024 + xe] : 0.f;
                        t[2][e] = ok ? img2[yo * 1024 + x]  : 0.f;
                        t[3][e] = ok ? img2[yo * 1024 + xe] : 0.f;
                        t[4][e] = ok ? img1[gy * 1024 + x]  : 0.f;
                        t[5][e] = ok ? img1[gy * 1024 + xe] : 0.f;
                        t[6][e] = ok ? img1[yo * 1024 + x]  : 0.f;
                    }
                    vA  = make_float4(t[0][0], t[0][1], t[0][2], t[0][3]);
                    vB  = make_float4(t[1][0], t[1][1], t[1][2], t[1][3]);
                    vC  = make_float4(t[2][0], t[2][1], t[2][2], t[2][3]);
                    vD  = make_float4(t[3][0], t[3][1], t[3][2], t[3][3]);
                    vP  = make_float4(t[4][0], t[4][1], t[4][2], t[4][3]);
                    vPx = make_float4(t[5][0], t[5][1], t[5][2], t[5][3]);
                    vPy = make_float4(t[6][0], t[6][1], t[6][2], t[6][3]);
                }
            }
            const int base = row * 40 + c4;
            *(float4*)&sraw[base]        = vA;
            *(float4*)&sraw[1200 + base] = vB;
            *(float4*)&sraw[2400 + base] = vC;
            *(float4*)&sraw[3600 + base] = vD;
            *(float4*)&sraw[4800 + base] = vP;
            *(float4*)&sraw[6000 + base] = vPx;
            *(float4*)&sraw[7200 + base] = vPy;
        }
        __syncthreads();

        // ---- Phase A: basis + vertical 7-tap from smem (2 cols x 2 rows/thread) ----
        const bool activeA = tid < 240;
        float2 a0[2], a1[2], a2[2], a3[2], a4[2];
        int cA = 0, gA = 0;
        if (activeA) {
            const int p2 = tid % 20;
            gA = tid / 20;             // 12 groups of 2 output rows
            cA = p2 * 2;
#pragma unroll
            for (int j = 0; j < 2; j++) {
                a0[j] = make_float2(0.f, 0.f); a1[j] = a0[j]; a2[j] = a0[j];
                a3[j] = a0[j]; a4[j] = a0[j];
            }
#pragma unroll
            for (int i = 0; i < 8; i++) {
                const int base = (gA * 2 + i) * 40 + cA;
                float2 A  = *(const float2*)&sraw[base];
                float2 B  = *(const float2*)&sraw[1200 + base];
                float2 C  = *(const float2*)&sraw[2400 + base];
                float2 D  = *(const float2*)&sraw[3600 + base];
                float2 P  = *(const float2*)&sraw[4800 + base];
                float2 Px = *(const float2*)&sraw[6000 + base];
                float2 Py = *(const float2*)&sraw[7200 + base];
                float2 v0, v1, v2, v3, v4;
                float t, u, w2;
                v0.x = A.x * A.x;                 v0.y = A.y * A.y;
                t = A.x - B.x; v1.x = t * t - v0.x;  t = A.y - B.y; v1.y = t * t - v0.y;
                t = A.x - C.x; v2.x = t * t - v0.x;  t = A.y - C.y; v2.y = t * t - v0.y;
                t = A.x - D.x; v3.x = t * t - v0.x;  t = A.y - D.y; v3.y = t * t - v0.y;
                u = P.x - Px.x; w2 = P.x - Py.x; v4.x = u * u + w2 * w2 + 2.f * P.x * P.x;
                u = P.y - Px.y; w2 = P.y - Py.y; v4.y = u * u + w2 * w2 + 2.f * P.y * P.y;
#pragma unroll
                for (int j = 0; j < 2; j++) {
                    const int k = i - j;
                    if (k >= 0 && k < 7) {
                        const float w = CW(k);
                        a0[j].x += w * v0.x; a0[j].y += w * v0.y;
                        a1[j].x += w * v1.x; a1[j].y += w * v1.y;
                        a2[j].x += w * v2.x; a2[j].y += w * v2.y;
                        a3[j].x += w * v3.x; a3[j].y += w * v3.y;
                        a4[j].x += w * v4.x; a4[j].y += w * v4.y;
                    }
                }
            }
        }
        __syncthreads();   // all raw reads done before sa overwrites sraw
        if (activeA) {
#pragma unroll
            for (int j = 0; j < 2; j++) {
                const int r = gA * 2 + j;
                *(float2*)&sraw[(0 * 24 + r) * 40 + cA] = a0[j];
                *(float2*)&sraw[(1 * 24 + r) * 40 + cA] = a1[j];
                *(float2*)&sraw[(2 * 24 + r) * 40 + cA] = a2[j];
                *(float2*)&sraw[(3 * 24 + r) * 40 + cA] = a3[j];
                *(float2*)&sraw[(4 * 24 + r) * 40 + cA] = a4[j];
            }
        }
        __syncthreads();

        // ---- Phase B: horizontal 7-tap (4 outputs/thread) + combine ----
        if (tid < 192) {
            const int seg = tid & 7;
            const int y = tid >> 3;
            const int x0 = seg * 4;
            float rb0[4], rax[4], ray[4], rad[4], rs1[4];
#pragma unroll
            for (int p = 0; p < 5; p++) {
                float wv[10];
                const int rb = (p * 24 + y) * 40 + x0;
                *(float4*)&wv[0] = *(const float4*)&sraw[rb];
                *(float4*)&wv[4] = *(const float4*)&sraw[rb + 4];
                *(float2*)&wv[8] = *(const float2*)&sraw[rb + 8];
                float o0 = 0, o1 = 0, o2 = 0, o3 = 0;
#pragma unroll
                for (int k = 0; k < 7; k++) {
                    const float w = CW(k);
                    o0 += w * wv[k];     o1 += w * wv[k + 1];
                    o2 += w * wv[k + 2]; o3 += w * wv[k + 3];
                }
                if (p == 0)      { rb0[0]=o0; rb0[1]=o1; rb0[2]=o2; rb0[3]=o3; }
                else if (p == 1) { rax[0]=o0; rax[1]=o1; rax[2]=o2; rax[3]=o3; }
                else if (p == 2) { ray[0]=o0; ray[1]=o1; ray[2]=o2; ray[3]=o3; }
                else if (p == 3) { rad[0]=o0; rad[1]=o1; rad[2]=o2; rad[3]=o3; }
                else             { rs1[0]=o0; rs1[1]=o1; rs1[2]=o2; rs1[3]=o3; }
            }
            const int oy = by0 + y;
            if (oy <= 1017) {
#pragma unroll
                for (int j = 0; j < 4; j++) {
                    const int ox = bx0 + x0 + j;
                    if (ox <= 1016) {
                        float vimg = rs1[j] * 0.25f + 1e-5f;
                        float inv = __fdividef(-1.4426950408889634f, vimg);
                        float t0 = rb0[j] * inv;
                        float t1 = (rb0[j] + rax[j]) * inv;
                        float t2 = (rb0[j] + ray[j]) * inv;
                        float t3 = (rb0[j] + rad[j]) * inv;
                        float tm = fmaxf(fmaxf(t0, t1), fmaxf(t2, t3));
                        psum += 77.f * ex2(t0 - tm) + ex2(t1 - tm)
                                     + ex2(t2 - tm) + ex2(t3 - tm);
                    }
                }
            }
        }
    } else {
        // ===================== GENERAL PATH (512-boundary tiles) =====================
        if (tid < 240) {
            const int c = tid % 40;
            const int g = tid / 40;
            const int gx = bx0 - 3 + c;
            const int gy0 = by0 - 3 + g * 4;
            const bool xok = gx < 1024;
            const int xo = gx ^ 512;
            float a0[4] = {0,0,0,0}, a1[4] = {0,0,0,0}, a2[4] = {0,0,0,0};
            float a2t[4] = {0,0,0,0}, a3[4] = {0,0,0,0}, a3t[4] = {0,0,0,0};
            float a4[4] = {0,0,0,0};
#pragma unroll
            for (int i = 0; i < 10; i++) {
                int gy = gy0 + i;
                float v0 = 0.f, v1 = 0.f, v2 = 0.f, v3 = 0.f, v4 = 0.f;
                if (xok && gy < 1024) {
                    int yo = gy ^ 512;
                    float a  = img2[gy * 1024 + gx];
                    float bx = img2[gy * 1024 + xo];
                    float by = img2[yo * 1024 + gx];
                    float bd = img2[yo * 1024 + xo];
                    v0 = a * a;
                    float t;
                    t = a - bx; v1 = t * t - v0;
                    t = a - by; v2 = t * t - v0;
                    t = a - bd; v3 = t * t - v0;
                    float p  = img1[gy * 1024 + gx];
                    float px = img1[gy * 1024 + xo];
                    float py = img1[yo * 1024 + gx];
                    float u = p - px, w = p - py;
                    v4 = u * u + w * w + 2.f * p * p;
                }
                const bool top = gy < 512;
                float v2t = top ? v2 : 0.f;
                float v3t = top ? v3 : 0.f;
#pragma unroll
                for (int j = 0; j < 4; j++) {
                    const int k = i - j;
                    if (k >= 0 && k < 7) {
                        const float w = CW(k);
                        a0[j] += w * v0;  a1[j] += w * v1;
                        a2[j] += w * v2;  a2t[j] += w * v2t;
                        a3[j] += w * v3;  a3t[j] += w * v3t;
                        a4[j] += w * v4;
                    }
                }
            }
#pragma unroll
            for (int j = 0; j < 4; j++) {
                const int r = g * 4 + j;
                sraw[(0 * 24 + r) * 40 + c] = a0[j];
                sraw[(1 * 24 + r) * 40 + c] = a1[j];
                sraw[(2 * 24 + r) * 40 + c] = a2[j];
                sraw[(3 * 24 + r) * 40 + c] = a2t[j];
                sraw[(4 * 24 + r) * 40 + c] = a3[j];
                sraw[(5 * 24 + r) * 40 + c] = a3t[j];
                sraw[(6 * 24 + r) * 40 + c] = a4[j];
            }
        }
        __syncthreads();

        if (tid < 192) {
            const int seg = tid & 7;
            const int y = tid >> 3;
            const int oy = by0 + y;
#pragma unroll
            for (int j = 0; j < 4; j++) {
                const int x = seg * 4 + j;
                const int ox = bx0 + x;
                float b0 = 0, hax = 0, haxL = 0, hay = 0, hayt = 0;
                float had = 0, hadL = 0, hadt = 0, hadtL = 0, hs1 = 0;
#pragma unroll
                for (int k = 0; k < 7; k++) {
                    const float w = CW(k);
                    const int cc = x + k;
                    bool left = (bx0 - 3 + cc) < 512;
                    b0 += w * sraw[(0 * 24 + y) * 40 + cc];
                    float vx = w * sraw[(1 * 24 + y) * 40 + cc]; hax += vx; haxL += left ? vx : 0.f;
                    hay  += w * sraw[(2 * 24 + y) * 40 + cc];
                    hayt += w * sraw[(3 * 24 + y) * 40 + cc];
                    float vd = w * sraw[(4 * 24 + y) * 40 + cc]; had += vd; hadL += left ? vd : 0.f;
                    float vt = w * sraw[(5 * 24 + y) * 40 + cc]; hadt += vt; hadtL += left ? vt : 0.f;
                    hs1 += w * sraw[(6 * 24 + y) * 40 + cc];
                }
                if (oy <= 1017 && ox <= 1016) {
                    float vimg = hs1 * 0.25f + 1e-5f;
                    float inv = __fdividef(-1.4426950408889634f, vimg);
                    float D[9];
                    D[0] = b0;
                    D[1] = b0 + haxL;
                    D[2] = b0 + hax - haxL;
                    D[3] = b0 + hayt;
                    D[4] = b0 + hay - hayt;
                    D[5] = b0 + hadtL;
                    D[6] = b0 + hadt - hadtL;
                    D[7] = b0 + hadL - hadtL;
                    D[8] = b0 + (had - hadL) - (hadt - hadtL);
                    float t[9];
#pragma unroll
                    for (int c2 = 0; c2 < 9; c2++) t[c2] = D[c2] * inv;
                    float tm = t[0];
#pragma unroll
                    for (int c2 = 1; c2 < 9; c2++) tm = fmaxf(tm, t[c2]);
                    float s = 72.f * ex2(t[0] - tm);
#pragma unroll
                    for (int c2 = 1; c2 < 9; c2++) s += ex2(t[c2] - tm);
                    psum += s;
                }
            }
        }
    }

    // ---- deterministic block reduction (shuffle tree) ----
    float v = psum;
#pragma unroll
    for (int o = 16; o > 0; o >>= 1) v += __shfl_xor_sync(0xffffffffu, v, o);
    if ((tid & 31) == 0) swr[tid >> 5] = v;
    __syncthreads();
    if (tid == 0) {
        float t = 0.f;
#pragma unroll
        for (int w = 0; w < 8; w++) t += swr[w];
        g_partials[blockIdx.y * NBX + blockIdx.x] = t;
        __threadfence();
        unsigned int n = atomicAdd(&g_count, 1u);
        s_last = (n == NBLK - 1);
    }
    __syncthreads();

    // ---- fused final reduction in the last-arriving block (fixed order) ----
    if (s_last) {
        float u = 0.f;
        for (int i = tid; i < NBLK; i += 256) u += g_partials[i];
#pragma unroll
        for (int o = 16; o > 0; o >>= 1) u += __shfl_xor_sync(0xffffffffu, u, o);
        if ((tid & 31) == 0) swr[tid >> 5] = u;
        __syncthreads();
        if (tid == 0) {
            float t = 0.f;
#pragma unroll
            for (int w = 0; w < 8; w++) t += swr[w];
            out[0] = t * (float)(1.0 / 81688800.0);  // mean over 80*1011*1010
            g_count = 0;   // reset for next graph replay
        }
    }
}

extern "C" void kernel_launch(void* const* d_in, const int* in_sizes, int n_in,
                              void* d_out, int out_size) {
    const float* img1 = (const float*)d_in[0];
    const float* img2 = (const float*)d_in[1];
    dim3 grid(NBX, NBY);
    mind_main<<<grid, 256>>>(img1, img2, (float*)d_out);
}

// round 5
// speedup vs baseline: 1.5163x; 1.2970x over previous
#include <cuda_runtime.h>

// MIND loss, 1024x1024, round 5.
//  - 72/80 channels identical; uniform tiles need only 4 distinct channels
//  - stage 5 BASIS planes (computed during LDG latency), not 7 raw regions
//  - Phase A: vertical 7-tap, scalar cols, 4-row rolling groups (2.5x reads)
//  - Phase B: horizontal 7-tap, 4 outputs/thread, float4 smem reads
//  - general (512-boundary) path shares the staged-basis scheme
//  - deterministic shuffle reductions, fused last-block finish

#define TX 32
#define TY 24
#define NBX 32
#define NBY 43
#define NBLK (NBX * NBY)

#define CW(k) ((k)==0 ? 0.06475879783294587f : \
               (k)==1 ? 0.12098536225957168f : \
               (k)==2 ? 0.17603266338214976f : \
               (k)==3 ? 0.19947114020071635f : \
               (k)==4 ? 0.17603266338214976f : \
               (k)==5 ? 0.12098536225957168f : \
                        0.06475879783294587f)

__device__ float g_partials[NBLK];
__device__ unsigned int g_count;

__device__ __forceinline__ float ex2(float x) {
    float r;
    asm("ex2.approx.ftz.f32 %0, %1;" : "=f"(r) : "f"(x));
    return r;
}

__global__ __launch_bounds__(256, 5)
void mind_main(const float* __restrict__ img1, const float* __restrict__ img2,
               float* __restrict__ out) {
    // Staging: 5 basis planes x 30 rows x 40 cols = 6000 floats.
    // After Phase A the same buffer holds the vertical-conv planes:
    // fast path 5 x 24 x 40 = 4800, general path 7 x 24 x 40 = 6720.
    __shared__ float sraw[6720];
    __shared__ float swr[8];
    __shared__ bool s_last;

    const int tid = threadIdx.x;
    const int bx0 = 7 + blockIdx.x * TX;
    const int by0 = 7 + blockIdx.y * TY;

    const bool xu = !((bx0 - 3) < 512 && (bx0 + 34) >= 512);
    const bool yu = !((by0 - 3) < 512 && (by0 + 26) >= 512);

    float psum = 0.f;

    // ================= Stage basis fields (both paths) =================
    for (int i = tid; i < 300; i += 256) {
        const int row = i / 10;
        const int c4 = (i - row * 10) * 4;
        const int gy = by0 - 3 + row;
        const int gx = bx0 - 3 + c4;
        const int yo = gy ^ 512;
        const int xo = gx ^ 512;
        float4 v0 = {0,0,0,0}, v1 = v0, v2 = v0, v3 = v0, v4 = v0;
        if (gy < 1024) {
            if (gx + 3 < 1024) {
                float4 A  = *(const float4*)(img2 + gy * 1024 + gx);
                float4 B  = *(const float4*)(img2 + gy * 1024 + xo);
                float4 C  = *(const float4*)(img2 + yo * 1024 + gx);
                float4 D  = *(const float4*)(img2 + yo * 1024 + xo);
                float4 P  = *(const float4*)(img1 + gy * 1024 + gx);
                float4 Px = *(const float4*)(img1 + gy * 1024 + xo);
                float4 Py = *(const float4*)(img1 + yo * 1024 + gx);
                float t, u, w;
                v0.x = A.x * A.x; v0.y = A.y * A.y; v0.z = A.z * A.z; v0.w = A.w * A.w;
                t = A.x - B.x; v1.x = t * t - v0.x;  t = A.y - B.y; v1.y = t * t - v0.y;
                t = A.z - B.z; v1.z = t * t - v0.z;  t = A.w - B.w; v1.w = t * t - v0.w;
                t = A.x - C.x; v2.x = t * t - v0.x;  t = A.y - C.y; v2.y = t * t - v0.y;
                t = A.z - C.z; v2.z = t * t - v0.z;  t = A.w - C.w; v2.w = t * t - v0.w;
                t = A.x - D.x; v3.x = t * t - v0.x;  t = A.y - D.y; v3.y = t * t - v0.y;
                t = A.z - D.z; v3.z = t * t - v0.z;  t = A.w - D.w; v3.w = t * t - v0.w;
                u = P.x - Px.x; w = P.x - Py.x; v4.x = u * u + w * w + 2.f * P.x * P.x;
                u = P.y - Px.y; w = P.y - Py.y; v4.y = u * u + w * w + 2.f * P.y * P.y;
                u = P.z - Px.z; w = P.z - Py.z; v4.z = u * u + w * w + 2.f * P.z * P.z;
                u = P.w - Px.w; w = P.w - Py.w; v4.w = u * u + w * w + 2.f * P.w * P.w;
            } else {
                float r0[4], r1[4], r2[4], r3[4], r4[4];
#pragma unroll
                for (int e = 0; e < 4; e++) {
                    int x = gx + e;
                    r0[e] = r1[e] = r2[e] = r3[e] = r4[e] = 0.f;
                    if (x < 1024) {
                        int xe = x ^ 512;
                        float a  = img2[gy * 1024 + x];
                        float b  = img2[gy * 1024 + xe];
                        float cc = img2[yo * 1024 + x];
                        float d  = img2[yo * 1024 + xe];
                        r0[e] = a * a;
                        float t;
                        t = a - b;  r1[e] = t * t - r0[e];
                        t = a - cc; r2[e] = t * t - r0[e];
                        t = a - d;  r3[e] = t * t - r0[e];
                        float p  = img1[gy * 1024 + x];
                        float px = img1[gy * 1024 + xe];
                        float py = img1[yo * 1024 + x];
                        float u = p - px, w = p - py;
                        r4[e] = u * u + w * w + 2.f * p * p;
                    }
                }
                v0 = make_float4(r0[0], r0[1], r0[2], r0[3]);
                v1 = make_float4(r1[0], r1[1], r1[2], r1[3]);
                v2 = make_float4(r2[0], r2[1], r2[2], r2[3]);
                v3 = make_float4(r3[0], r3[1], r3[2], r3[3]);
                v4 = make_float4(r4[0], r4[1], r4[2], r4[3]);
            }
        }
        const int base = row * 40 + c4;
        *(float4*)&sraw[base]        = v0;
        *(float4*)&sraw[1200 + base] = v1;
        *(float4*)&sraw[2400 + base] = v2;
        *(float4*)&sraw[3600 + base] = v3;
        *(float4*)&sraw[4800 + base] = v4;
    }
    __syncthreads();

    if (xu && yu) {
        // ===================== FAST PATH =====================
        // ---- Phase A: vertical 7-tap, 40 cols x 6 groups of 4 rows ----
        const bool act = tid < 240;
        float a0[4], a1[4], a2[4], a3[4], a4[4];
        int cA = 0, gA = 0;
        if (act) {
            cA = tid % 40;
            gA = tid / 40;
#pragma unroll
            for (int j = 0; j < 4; j++) { a0[j]=0;a1[j]=0;a2[j]=0;a3[j]=0;a4[j]=0; }
#pragma unroll
            for (int i = 0; i < 10; i++) {
                const int base = (gA * 4 + i) * 40 + cA;
                float v0 = sraw[base];
                float v1 = sraw[1200 + base];
                float v2 = sraw[2400 + base];
                float v3 = sraw[3600 + base];
                float v4 = sraw[4800 + base];
#pragma unroll
                for (int j = 0; j < 4; j++) {
                    const int k = i - j;
                    if (k >= 0 && k < 7) {
                        const float w = CW(k);
                        a0[j] += w * v0; a1[j] += w * v1; a2[j] += w * v2;
                        a3[j] += w * v3; a4[j] += w * v4;
                    }
                }
            }
        }
        __syncthreads();   // all staged reads done before overwrite
        if (act) {
#pragma unroll
            for (int j = 0; j < 4; j++) {
                const int r = gA * 4 + j;
                sraw[(0 * 24 + r) * 40 + cA] = a0[j];
                sraw[(1 * 24 + r) * 40 + cA] = a1[j];
                sraw[(2 * 24 + r) * 40 + cA] = a2[j];
                sraw[(3 * 24 + r) * 40 + cA] = a3[j];
                sraw[(4 * 24 + r) * 40 + cA] = a4[j];
            }
        }
        __syncthreads();

        // ---- Phase B: horizontal 7-tap (4 outputs/thread) + combine ----
        if (tid < 192) {
            const int seg = tid & 7;
            const int y = tid >> 3;
            const int x0 = seg * 4;
            float rb0[4], rax[4], ray[4], rad[4], rs1[4];
#pragma unroll
            for (int p = 0; p < 5; p++) {
                float wv[10];
                const int rb = (p * 24 + y) * 40 + x0;
                *(float4*)&wv[0] = *(const float4*)&sraw[rb];
                *(float4*)&wv[4] = *(const float4*)&sraw[rb + 4];
                *(float2*)&wv[8] = *(const float2*)&sraw[rb + 8];
                float o0 = 0, o1 = 0, o2 = 0, o3 = 0;
#pragma unroll
                for (int k = 0; k < 7; k++) {
                    const float w = CW(k);
                    o0 += w * wv[k];     o1 += w * wv[k + 1];
                    o2 += w * wv[k + 2]; o3 += w * wv[k + 3];
                }
                if (p == 0)      { rb0[0]=o0; rb0[1]=o1; rb0[2]=o2; rb0[3]=o3; }
                else if (p == 1) { rax[0]=o0; rax[1]=o1; rax[2]=o2; rax[3]=o3; }
                else if (p == 2) { ray[0]=o0; ray[1]=o1; ray[2]=o2; ray[3]=o3; }
                else if (p == 3) { rad[0]=o0; rad[1]=o1; rad[2]=o2; rad[3]=o3; }
                else             { rs1[0]=o0; rs1[1]=o1; rs1[2]=o2; rs1[3]=o3; }
            }
            const int oy = by0 + y;
            if (oy <= 1017) {
#pragma unroll
                for (int j = 0; j < 4; j++) {
                    const int ox = bx0 + x0 + j;
                    if (ox <= 1016) {
                        float vimg = rs1[j] * 0.25f + 1e-5f;
                        float inv = __fdividef(-1.4426950408889634f, vimg);
                        float t0 = rb0[j] * inv;
                        float t1 = (rb0[j] + rax[j]) * inv;
                        float t2 = (rb0[j] + ray[j]) * inv;
                        float t3 = (rb0[j] + rad[j]) * inv;
                        float tm = fmaxf(fmaxf(t0, t1), fmaxf(t2, t3));
                        psum += 77.f * ex2(t0 - tm) + ex2(t1 - tm)
                                     + ex2(t2 - tm) + ex2(t3 - tm);
                    }
                }
            }
        }
    } else {
        // ===================== GENERAL PATH (512-boundary tiles) =====================
        // ---- Phase A: vertical 7-tap with top-masked variants, 7 planes ----
        const bool act = tid < 240;
        float a0[4], a1[4], a2[4], a2t[4], a3[4], a3t[4], a4[4];
        int cA = 0, gA = 0;
        if (act) {
            cA = tid % 40;
            gA = tid / 40;
#pragma unroll
            for (int j = 0; j < 4; j++) {
                a0[j]=0;a1[j]=0;a2[j]=0;a2t[j]=0;a3[j]=0;a3t[j]=0;a4[j]=0;
            }
#pragma unroll
            for (int i = 0; i < 10; i++) {
                const int row = gA * 4 + i;
                const int base = row * 40 + cA;
                float v0 = sraw[base];
                float v1 = sraw[1200 + base];
                float v2 = sraw[2400 + base];
                float v3 = sraw[3600 + base];
                float v4 = sraw[4800 + base];
                const bool top = (by0 - 3 + row) < 512;
                float v2t = top ? v2 : 0.f;
                float v3t = top ? v3 : 0.f;
#pragma unroll
                for (int j = 0; j < 4; j++) {
                    const int k = i - j;
                    if (k >= 0 && k < 7) {
                        const float w = CW(k);
                        a0[j] += w * v0;  a1[j] += w * v1;
                        a2[j] += w * v2;  a2t[j] += w * v2t;
                        a3[j] += w * v3;  a3t[j] += w * v3t;
                        a4[j] += w * v4;
                    }
                }
            }
        }
        __syncthreads();
        if (act) {
#pragma unroll
            for (int j = 0; j < 4; j++) {
                const int r = gA * 4 + j;
                sraw[(0 * 24 + r) * 40 + cA] = a0[j];
                sraw[(1 * 24 + r) * 40 + cA] = a1[j];
                sraw[(2 * 24 + r) * 40 + cA] = a2[j];
                sraw[(3 * 24 + r) * 40 + cA] = a2t[j];
                sraw[(4 * 24 + r) * 40 + cA] = a3[j];
                sraw[(5 * 24 + r) * 40 + cA] = a3t[j];
                sraw[(6 * 24 + r) * 40 + cA] = a4[j];
            }
        }
        __syncthreads();

        // ---- Phase B: masked horizontal pass + 9-channel combine ----
        if (tid < 192) {
            const int seg = tid & 7;
            const int y = tid >> 3;
            const int oy = by0 + y;
#pragma unroll
            for (int j = 0; j < 4; j++) {
                const int x = seg * 4 + j;
                const int ox = bx0 + x;
                float b0 = 0, hax = 0, haxL = 0, hay = 0, hayt = 0;
                float had = 0, hadL = 0, hadt = 0, hadtL = 0, hs1 = 0;
#pragma unroll
                for (int k = 0; k < 7; k++) {
                    const float w = CW(k);
                    const int cc = x + k;
                    bool left = (bx0 - 3 + cc) < 512;
                    b0 += w * sraw[(0 * 24 + y) * 40 + cc];
                    float vx = w * sraw[(1 * 24 + y) * 40 + cc]; hax += vx; haxL += left ? vx : 0.f;
                    hay  += w * sraw[(2 * 24 + y) * 40 + cc];
                    hayt += w * sraw[(3 * 24 + y) * 40 + cc];
                    float vd = w * sraw[(4 * 24 + y) * 40 + cc]; had += vd; hadL += left ? vd : 0.f;
                    float vt = w * sraw[(5 * 24 + y) * 40 + cc]; hadt += vt; hadtL += left ? vt : 0.f;
                    hs1 += w * sraw[(6 * 24 + y) * 40 + cc];
                }
                if (oy <= 1017 && ox <= 1016) {
                    float vimg = hs1 * 0.25f + 1e-5f;
                    float inv = __fdividef(-1.4426950408889634f, vimg);
                    float D[9];
                    D[0] = b0;
                    D[1] = b0 + haxL;
                    D[2] = b0 + hax - haxL;
                    D[3] = b0 + hayt;
                    D[4] = b0 + hay - hayt;
                    D[5] = b0 + hadtL;
                    D[6] = b0 + hadt - hadtL;
                    D[7] = b0 + hadL - hadtL;
                    D[8] = b0 + (had - hadL) - (hadt - hadtL);
                    float t[9];
#pragma unroll
                    for (int c2 = 0; c2 < 9; c2++) t[c2] = D[c2] * inv;
                    float tm = t[0];
#pragma unroll
                    for (int c2 = 1; c2 < 9; c2++) tm = fmaxf(tm, t[c2]);
                    float s = 72.f * ex2(t[0] - tm);
#pragma unroll
                    for (int c2 = 1; c2 < 9; c2++) s += ex2(t[c2] - tm);
                    psum += s;
                }
            }
        }
    }

    // ---- deterministic block reduction (shuffle tree) ----
    float v = psum;
#pragma unroll
    for (int o = 16; o > 0; o >>= 1) v += __shfl_xor_sync(0xffffffffu, v, o);
    if ((tid & 31) == 0) swr[tid >> 5] = v;
    __syncthreads();
    if (tid == 0) {
        float t = 0.f;
#pragma unroll
        for (int w = 0; w < 8; w++) t += swr[w];
        g_partials[blockIdx.y * NBX + blockIdx.x] = t;
        __threadfence();
        unsigned int n = atomicAdd(&g_count, 1u);
        s_last = (n == NBLK - 1);
    }
    __syncthreads();

    // ---- fused final reduction in the last-arriving block (fixed order) ----
    if (s_last) {
        float u = 0.f;
        for (int i = tid; i < NBLK; i += 256) u += g_partials[i];
#pragma unroll
        for (int o = 16; o > 0; o >>= 1) u += __shfl_xor_sync(0xffffffffu, u, o);
        if ((tid & 31) == 0) swr[tid >> 5] = u;
        __syncthreads();
        if (tid == 0) {
            float t = 0.f;
#pragma unroll
            for (int w = 0; w < 8; w++) t += swr[w];
            out[0] = t * (float)(1.0 / 81688800.0);  // mean over 80*1011*1010
            g_count = 0;   // reset for next graph replay
        }
    }
}

extern "C" void kernel_launch(void* const* d_in, const int* in_sizes, int n_in,
                              void* d_out, int out_size) {
    const float* img1 = (const float*)d_in[0];
    const float* img2 = (const float*)d_in[1];
    dim3 grid(NBX, NBY);
    mind_main<<<grid, 256>>>(img1, img2, (float*)d_out);
}

// round 6
// speedup vs baseline: 1.6250x; 1.0717x over previous
#include <cuda_runtime.h>

// MIND loss, 1024x1024, round 6.
//  - 72/80 channels identical; uniform tiles need only 4 distinct channels
//  - stage 5 basis planes (computed during LDG latency), plane stride 1224
//    (==8 mod 32 -> conflict-free (plane,col) warp mapping)
//  - Phase A: TRUE rolling vertical 7-tap, thread=(plane,col), each staged
//    value read exactly once (redundancy 1.0x), outputs in registers,
//    stored in-place over staged rows 0..23
//  - Phase B: horizontal 7-tap, 4 outputs/thread, float4 smem reads
//  - deterministic shuffle reductions, fused last-block finish

#define TX 32
#define TY 24
#define NBX 32
#define NBY 43
#define NBLK (NBX * NBY)

#define PSTR 1224          // plane stride in floats (==8 mod 32, ==0 mod 4)
#define G2T  6120          // general-path scratch plane: a2t
#define G3T  7080          // general-path scratch plane: a3t

#define CW(k) ((k)==0 ? 0.06475879783294587f : \
               (k)==1 ? 0.12098536225957168f : \
               (k)==2 ? 0.17603266338214976f : \
               (k)==3 ? 0.19947114020071635f : \
               (k)==4 ? 0.17603266338214976f : \
               (k)==5 ? 0.12098536225957168f : \
                        0.06475879783294587f)

__device__ float g_partials[NBLK];
__device__ unsigned int g_count;

__device__ __forceinline__ float ex2(float x) {
    float r;
    asm("ex2.approx.ftz.f32 %0, %1;" : "=f"(r) : "f"(x));
    return r;
}

__global__ __launch_bounds__(256, 5)
void mind_main(const float* __restrict__ img1, const float* __restrict__ img2,
               float* __restrict__ out) {
    __shared__ float sraw[8064];
    __shared__ float swr[8];
    __shared__ bool s_last;

    const int tid = threadIdx.x;
    const int bx0 = 7 + blockIdx.x * TX;
    const int by0 = 7 + blockIdx.y * TY;

    const bool xu = !((bx0 - 3) < 512 && (bx0 + 34) >= 512);
    const bool yu = !((by0 - 3) < 512 && (by0 + 26) >= 512);

    float psum = 0.f;

    // ================= Stage basis fields (both paths) =================
    for (int i = tid; i < 300; i += 256) {
        const int row = i / 10;
        const int c4 = (i - row * 10) * 4;
        const int gy = by0 - 3 + row;
        const int gx = bx0 - 3 + c4;
        const int yo = gy ^ 512;
        const int xo = gx ^ 512;
        float4 v0 = {0,0,0,0}, v1 = v0, v2 = v0, v3 = v0, v4 = v0;
        if (gy < 1024) {
            if (gx + 3 < 1024) {
                float4 A  = *(const float4*)(img2 + gy * 1024 + gx);
                float4 B  = *(const float4*)(img2 + gy * 1024 + xo);
                float4 C  = *(const float4*)(img2 + yo * 1024 + gx);
                float4 D  = *(const float4*)(img2 + yo * 1024 + xo);
                float4 P  = *(const float4*)(img1 + gy * 1024 + gx);
                float4 Px = *(const float4*)(img1 + gy * 1024 + xo);
                float4 Py = *(const float4*)(img1 + yo * 1024 + gx);
                float t, u, w;
                v0.x = A.x * A.x; v0.y = A.y * A.y; v0.z = A.z * A.z; v0.w = A.w * A.w;
                t = A.x - B.x; v1.x = t * t - v0.x;  t = A.y - B.y; v1.y = t * t - v0.y;
                t = A.z - B.z; v1.z = t * t - v0.z;  t = A.w - B.w; v1.w = t * t - v0.w;
                t = A.x - C.x; v2.x = t * t - v0.x;  t = A.y - C.y; v2.y = t * t - v0.y;
                t = A.z - C.z; v2.z = t * t - v0.z;  t = A.w - C.w; v2.w = t * t - v0.w;
                t = A.x - D.x; v3.x = t * t - v0.x;  t = A.y - D.y; v3.y = t * t - v0.y;
                t = A.z - D.z; v3.z = t * t - v0.z;  t = A.w - D.w; v3.w = t * t - v0.w;
                u = P.x - Px.x; w = P.x - Py.x; v4.x = u * u + w * w + 2.f * P.x * P.x;
                u = P.y - Px.y; w = P.y - Py.y; v4.y = u * u + w * w + 2.f * P.y * P.y;
                u = P.z - Px.z; w = P.z - Py.z; v4.z = u * u + w * w + 2.f * P.z * P.z;
                u = P.w - Px.w; w = P.w - Py.w; v4.w = u * u + w * w + 2.f * P.w * P.w;
            } else {
                float r0[4], r1[4], r2[4], r3[4], r4[4];
#pragma unroll
                for (int e = 0; e < 4; e++) {
                    int x = gx + e;
                    r0[e] = r1[e] = r2[e] = r3[e] = r4[e] = 0.f;
                    if (x < 1024) {
                        int xe = x ^ 512;
                        float a  = img2[gy * 1024 + x];
                        float b  = img2[gy * 1024 + xe];
                        float cc = img2[yo * 1024 + x];
                        float d  = img2[yo * 1024 + xe];
                        r0[e] = a * a;
                        float t;
                        t = a - b;  r1[e] = t * t - r0[e];
                        t = a - cc; r2[e] = t * t - r0[e];
                        t = a - d;  r3[e] = t * t - r0[e];
                        float p  = img1[gy * 1024 + x];
                        float px = img1[gy * 1024 + xe];
                        float py = img1[yo * 1024 + x];
                        float u = p - px, w = p - py;
                        r4[e] = u * u + w * w + 2.f * p * p;
                    }
                }
                v0 = make_float4(r0[0], r0[1], r0[2], r0[3]);
                v1 = make_float4(r1[0], r1[1], r1[2], r1[3]);
                v2 = make_float4(r2[0], r2[1], r2[2], r2[3]);
                v3 = make_float4(r3[0], r3[1], r3[2], r3[3]);
                v4 = make_float4(r4[0], r4[1], r4[2], r4[3]);
            }
        }
        const int base = row * 40 + c4;
        *(float4*)&sraw[0 * PSTR + base] = v0;
        *(float4*)&sraw[1 * PSTR + base] = v1;
        *(float4*)&sraw[2 * PSTR + base] = v2;
        *(float4*)&sraw[3 * PSTR + base] = v3;
        *(float4*)&sraw[4 * PSTR + base] = v4;
    }
    __syncthreads();

    if (xu && yu) {
        // ===================== FAST PATH =====================
        // ---- Phase A: rolling vertical 7-tap, thread = (plane, col) ----
        float o[24];
        unsigned pb = 0;
        const bool act = tid < 200;
        if (act) {
            const int pl = tid / 40;
            const int cA = tid - pl * 40;
            pb = pl * PSTR + cA;
#pragma unroll
            for (int r = 0; r < 24; r++) o[r] = 0.f;
#pragma unroll
            for (int i = 0; i < 30; i++) {
                const float v = sraw[pb + i * 40];
#pragma unroll
                for (int d = 0; d < 7; d++) {
                    const int r = i - d;
                    if (r >= 0 && r < 24) o[r] += CW(d) * v;
                }
            }
        }
        __syncthreads();   // all staged reads done before in-place overwrite
        if (act) {
#pragma unroll
            for (int r = 0; r < 24; r++) sraw[pb + r * 40] = o[r];
        }
        __syncthreads();

        // ---- Phase B: horizontal 7-tap (4 outputs/thread) + combine ----
        if (tid < 192) {
            const int seg = tid & 7;
            const int y = tid >> 3;
            const int x0 = seg * 4;
            float rb0[4], rax[4], ray[4], rad[4], rs1[4];
#pragma unroll
            for (int p = 0; p < 5; p++) {
                float wv[10];
                const int rb = p * PSTR + y * 40 + x0;
                *(float4*)&wv[0] = *(const float4*)&sraw[rb];
                *(float4*)&wv[4] = *(const float4*)&sraw[rb + 4];
                *(float2*)&wv[8] = *(const float2*)&sraw[rb + 8];
                float o0 = 0, o1 = 0, o2 = 0, o3 = 0;
#pragma unroll
                for (int k = 0; k < 7; k++) {
                    const float w = CW(k);
                    o0 += w * wv[k];     o1 += w * wv[k + 1];
                    o2 += w * wv[k + 2]; o3 += w * wv[k + 3];
                }
                if (p == 0)      { rb0[0]=o0; rb0[1]=o1; rb0[2]=o2; rb0[3]=o3; }
                else if (p == 1) { rax[0]=o0; rax[1]=o1; rax[2]=o2; rax[3]=o3; }
                else if (p == 2) { ray[0]=o0; ray[1]=o1; ray[2]=o2; ray[3]=o3; }
                else if (p == 3) { rad[0]=o0; rad[1]=o1; rad[2]=o2; rad[3]=o3; }
                else             { rs1[0]=o0; rs1[1]=o1; rs1[2]=o2; rs1[3]=o3; }
            }
            const int oy = by0 + y;
            if (oy <= 1017) {
#pragma unroll
                for (int j = 0; j < 4; j++) {
                    const int ox = bx0 + x0 + j;
                    if (ox <= 1016) {
                        float vimg = rs1[j] * 0.25f + 1e-5f;
                        float inv = __fdividef(-1.4426950408889634f, vimg);
                        float t0 = rb0[j] * inv;
                        float t1 = (rb0[j] + rax[j]) * inv;
                        float t2 = (rb0[j] + ray[j]) * inv;
                        float t3 = (rb0[j] + rad[j]) * inv;
                        float tm = fmaxf(fmaxf(t0, t1), fmaxf(t2, t3));
                        psum += 77.f * ex2(t0 - tm) + ex2(t1 - tm)
                                     + ex2(t2 - tm) + ex2(t3 - tm);
                    }
                }
            }
        }
    } else {
        // ===================== GENERAL PATH (512-boundary tiles) =====================
        // ---- Phase A: vertical 7-tap with top-masked variants (R5 scheme) ----
        const bool act = tid < 240;
        float a0[4], a1[4], a2[4], a2t[4], a3[4], a3t[4], a4[4];
        int cA = 0, gA = 0;
        if (act) {
            cA = tid % 40;
            gA = tid / 40;
#pragma unroll
            for (int j = 0; j < 4; j++) {
                a0[j]=0;a1[j]=0;a2[j]=0;a2t[j]=0;a3[j]=0;a3t[j]=0;a4[j]=0;
            }
#pragma unroll
            for (int i = 0; i < 10; i++) {
                const int row = gA * 4 + i;
                const int base = row * 40 + cA;
                float v0 = sraw[0 * PSTR + base];
                float v1 = sraw[1 * PSTR + base];
                float v2 = sraw[2 * PSTR + base];
                float v3 = sraw[3 * PSTR + base];
                float v4 = sraw[4 * PSTR + base];
                const bool top = (by0 - 3 + row) < 512;
                float v2t = top ? v2 : 0.f;
                float v3t = top ? v3 : 0.f;
#pragma unroll
                for (int j = 0; j < 4; j++) {
                    const int k = i - j;
                    if (k >= 0 && k < 7) {
                        const float w = CW(k);
                        a0[j] += w * v0;  a1[j] += w * v1;
                        a2[j] += w * v2;  a2t[j] += w * v2t;
                        a3[j] += w * v3;  a3t[j] += w * v3t;
                        a4[j] += w * v4;
                    }
                }
            }
        }
        __syncthreads();
        if (act) {
#pragma unroll
            for (int j = 0; j < 4; j++) {
                const int r = gA * 4 + j;
                const int rc = r * 40 + cA;
                sraw[0 * PSTR + rc] = a0[j];
                sraw[1 * PSTR + rc] = a1[j];
                sraw[2 * PSTR + rc] = a2[j];
                sraw[3 * PSTR + rc] = a3[j];
                sraw[4 * PSTR + rc] = a4[j];
                sraw[G2T + rc] = a2t[j];
                sraw[G3T + rc] = a3t[j];
            }
        }
        __syncthreads();

        // ---- Phase B: masked horizontal pass + 9-channel combine ----
        if (tid < 192) {
            const int seg = tid & 7;
            const int y = tid >> 3;
            const int oy = by0 + y;
#pragma unroll
            for (int j = 0; j < 4; j++) {
                const int x = seg * 4 + j;
                const int ox = bx0 + x;
                float b0 = 0, hax = 0, haxL = 0, hay = 0, hayt = 0;
                float had = 0, hadL = 0, hadt = 0, hadtL = 0, hs1 = 0;
#pragma unroll
                for (int k = 0; k < 7; k++) {
                    const float w = CW(k);
                    const int cc = x + k;
                    const int yc = y * 40 + cc;
                    bool left = (bx0 - 3 + cc) < 512;
                    b0 += w * sraw[0 * PSTR + yc];
                    float vx = w * sraw[1 * PSTR + yc]; hax += vx; haxL += left ? vx : 0.f;
                    hay  += w * sraw[2 * PSTR + yc];
                    hayt += w * sraw[G2T + yc];
                    float vd = w * sraw[3 * PSTR + yc]; had += vd; hadL += left ? vd : 0.f;
                    float vt = w * sraw[G3T + yc]; hadt += vt; hadtL += left ? vt : 0.f;
                    hs1 += w * sraw[4 * PSTR + yc];
                }
                if (oy <= 1017 && ox <= 1016) {
                    float vimg = hs1 * 0.25f + 1e-5f;
                    float inv = __fdividef(-1.4426950408889634f, vimg);
                    float D[9];
                    D[0] = b0;
                    D[1] = b0 + haxL;
                    D[2] = b0 + hax - haxL;
                    D[3] = b0 + hayt;
                    D[4] = b0 + hay - hayt;
                    D[5] = b0 + hadtL;
                    D[6] = b0 + hadt - hadtL;
                    D[7] = b0 + hadL - hadtL;
                    D[8] = b0 + (had - hadL) - (hadt - hadtL);
                    float t[9];
#pragma unroll
                    for (int c2 = 0; c2 < 9; c2++) t[c2] = D[c2] * inv;
                    float tm = t[0];
#pragma unroll
                    for (int c2 = 1; c2 < 9; c2++) tm = fmaxf(tm, t[c2]);
                    float s = 72.f * ex2(t[0] - tm);
#pragma unroll
                    for (int c2 = 1; c2 < 9; c2++) s += ex2(t[c2] - tm);
                    psum += s;
                }
            }
        }
    }

    // ---- deterministic block reduction (shuffle tree) ----
    float v = psum;
#pragma unroll
    for (int o2 = 16; o2 > 0; o2 >>= 1) v += __shfl_xor_sync(0xffffffffu, v, o2);
    if ((tid & 31) == 0) swr[tid >> 5] = v;
    __syncthreads();
    if (tid == 0) {
        float t = 0.f;
#pragma unroll
        for (int w = 0; w < 8; w++) t += swr[w];
        g_partials[blockIdx.y * NBX + blockIdx.x] = t;
        __threadfence();
        unsigned int n = atomicAdd(&g_count, 1u);
        s_last = (n == NBLK - 1);
    }
    __syncthreads();

    // ---- fused final reduction in the last-arriving block (fixed order) ----
    if (s_last) {
        float u = 0.f;
        for (int i = tid; i < NBLK; i += 256) u += g_partials[i];
#pragma unroll
        for (int o2 = 16; o2 > 0; o2 >>= 1) u += __shfl_xor_sync(0xffffffffu, u, o2);
        if ((tid & 31) == 0) swr[tid >> 5] = u;
        __syncthreads();
        if (tid == 0) {
            float t = 0.f;
#pragma unroll
            for (int w = 0; w < 8; w++) t += swr[w];
            out[0] = t * (float)(1.0 / 81688800.0);  // mean over 80*1011*1010
            g_count = 0;   // reset for next graph replay
        }
    }
}

extern "C" void kernel_launch(void* const* d_in, const int* in_sizes, int n_in,
                              void* d_out, int out_size) {
    const float* img1 = (const float*)d_in[0];
    const float* img2 = (const float*)d_in[1];
    dim3 grid(NBX, NBY);
    mind_main<<<grid, 256>>>(img1, img2, (float*)d_out);
}